// round 5
// baseline (speedup 1.0000x reference)
#include <cuda_runtime.h>
#include <cuda_bf16.h>
#include <cstdint>

// Problem constants (fixed by the dataset)
#define BROWS   32768
#define MDIM    512
#define HDIM    256
#define TOTROWS (2 * BROWS)   // both branches stacked

// ---------------------------------------------------------------------------
// Scratch (static device allocations — no cudaMalloc allowed)
// ---------------------------------------------------------------------------
__device__ __align__(16) __nv_bfloat16 g_xhi [(size_t)BROWS * MDIM];
__device__ __align__(16) __nv_bfloat16 g_xlo [(size_t)BROWS * MDIM];
__device__ __align__(16) __nv_bfloat16 g_xchi[(size_t)BROWS * MDIM];
__device__ __align__(16) __nv_bfloat16 g_xclo[(size_t)BROWS * MDIM];
__device__ __align__(16) __nv_bfloat16 g_a0hi[(size_t)TOTROWS * HDIM];
__device__ __align__(16) __nv_bfloat16 g_a0lo[(size_t)TOTROWS * HDIM];
__device__ __align__(16) __nv_bfloat16 g_a1hi[(size_t)TOTROWS * HDIM];
__device__ __align__(16) __nv_bfloat16 g_a1lo[(size_t)TOTROWS * HDIM];
// Weights, fragment-major bf16 planes (u32 = 2 bf16 along k), v4-grouped pairs
__device__ __align__(16) uint32_t g_Wf0p[2][(size_t)MDIM * 128];
__device__ __align__(16) uint32_t g_WfHp[5][2][(size_t)HDIM * 128];

// ---------------------------------------------------------------------------
// Helpers
// ---------------------------------------------------------------------------
__device__ __forceinline__ uint32_t smem_u32(const void* p) {
    uint32_t a;
    asm("{ .reg .u64 t; cvta.to.shared.u64 t, %1; cvt.u32.u64 %0, t; }"
        : "=r"(a) : "l"(p));
    return a;
}
__device__ __forceinline__ void mma_bf16(float* d, const uint32_t* a,
                                         uint32_t b0, uint32_t b1) {
    asm volatile(
        "mma.sync.aligned.m16n8k16.row.col.f32.bf16.bf16.f32 "
        "{%0,%1,%2,%3}, {%4,%5,%6,%7}, {%8,%9}, {%0,%1,%2,%3};"
        : "+f"(d[0]), "+f"(d[1]), "+f"(d[2]), "+f"(d[3])
        : "r"(a[0]), "r"(a[1]), "r"(a[2]), "r"(a[3]), "r"(b0), "r"(b1));
}
__device__ __forceinline__ void ldsm4(uint32_t* r, uint32_t addr) {
    asm volatile("ldmatrix.sync.aligned.m8n8.x4.shared.b16 {%0,%1,%2,%3}, [%4];"
                 : "=r"(r[0]), "=r"(r[1]), "=r"(r[2]), "=r"(r[3]) : "r"(addr));
}
#define CP_ASYNC16(dst, src) \
    asm volatile("cp.async.cg.shared.global [%0], [%1], 16;" :: "r"(dst), "l"(src))
#define CP_COMMIT() asm volatile("cp.async.commit_group;" ::: "memory")
#define CP_WAIT0()  asm volatile("cp.async.wait_group 0;" ::: "memory")

// split fp32 -> hi bf16 + lo bf16 (hi exact subtract)
__device__ __forceinline__ void split2(float v, __nv_bfloat16& h, __nv_bfloat16& l) {
    h = __float2bfloat16_rn(v);
    l = __float2bfloat16_rn(v - __bfloat162float(h));
}
__device__ __forceinline__ uint32_t pack2(__nv_bfloat16 a, __nv_bfloat16 b) {
    return (uint32_t)__bfloat16_as_ushort(a) |
           ((uint32_t)__bfloat16_as_ushort(b) << 16);
}

// ---------------------------------------------------------------------------
// Corruption kernel (rank-q logic validated rel_err = 0.0 in R1);
// emits hi/lo bf16 planes for x and xc.
// ---------------------------------------------------------------------------
__global__ void __launch_bounds__(256) corrupt_kernel(
    const float* __restrict__ x, const float* __restrict__ u,
    const float* __restrict__ r, const float* __restrict__ low,
    const float* __restrict__ high, const int* __restrict__ qptr, int qdef,
    __nv_bfloat16* __restrict__ xhi, __nv_bfloat16* __restrict__ xlo,
    __nv_bfloat16* __restrict__ xchi, __nv_bfloat16* __restrict__ xclo)
{
    __shared__ float us[MDIM];
    __shared__ int   hist[1024];
    __shared__ int   s_bin, s_rank, s_cnt;
    __shared__ unsigned long long cand[48];
    __shared__ unsigned long long s_thresh;

    const int row = blockIdx.x;
    const int tid = threadIdx.x;
    const size_t base = (size_t)row * MDIM;

    int q = qptr ? *qptr : qdef;

    for (int j = tid; j < MDIM; j += 256) us[j] = u[base + j];
    for (int j = tid; j < 1024; j += 256) hist[j] = 0;
    __syncthreads();

    if (q <= 0) {
        if (tid == 0) s_thresh = 0ULL;
    } else if (q >= MDIM) {
        if (tid == 0) s_thresh = ~0ULL;
    }

    if (q > 0 && q < MDIM) {
        for (int j = tid; j < MDIM; j += 256) {
            float v = us[j];
            int b = (int)(v * 1024.0f);
            b = b < 0 ? 0 : (b > 1023 ? 1023 : b);
            atomicAdd(&hist[b], 1);
        }
        __syncthreads();

        if (tid < 32) {
            int s = 0;
            const int b0 = tid * 32;
            #pragma unroll
            for (int b = 0; b < 32; b++) s += hist[b0 + b];
            int pre = s;
            #pragma unroll
            for (int o = 1; o < 32; o <<= 1) {
                int n = __shfl_up_sync(0xffffffffu, pre, o);
                if (tid >= o) pre += n;
            }
            int excl = pre - s;
            if (q >= excl && q < excl + s) {
                int c = excl;
                for (int b = b0; b < b0 + 32; b++) {
                    int h = hist[b];
                    if (q < c + h) { s_bin = b; s_rank = q - c; break; }
                    c += h;
                }
            }
            if (tid == 0) s_cnt = 0;
        }
        __syncthreads();

        const int bsel = s_bin;
        for (int j = tid; j < MDIM; j += 256) {
            float v = us[j];
            int b = (int)(v * 1024.0f);
            b = b < 0 ? 0 : (b > 1023 ? 1023 : b);
            if (b == bsel) {
                int idx = atomicAdd(&s_cnt, 1);
                if (idx < 48)
                    cand[idx] = ((unsigned long long)__float_as_uint(v) << 9)
                                | (unsigned)j;
            }
        }
        __syncthreads();

        if (tid == 0) {
            int cnt = s_cnt < 48 ? s_cnt : 48;
            int rk = s_rank;
            unsigned long long th = 0ULL;
            for (int i = 0; i < cnt; i++) {
                int c = 0;
                for (int k2 = 0; k2 < cnt; k2++) c += (cand[k2] < cand[i]);
                if (c == rk) th = cand[i];
            }
            s_thresh = th;
        }
    }
    __syncthreads();

    const unsigned long long th = s_thresh;
    // each thread handles a consecutive pair of features -> u32 plane stores
    const int j0 = tid * 2, j1 = j0 + 1;
    float v0 = us[j0], v1 = us[j1];
    unsigned long long k0 =
        ((unsigned long long)__float_as_uint(v0) << 9) | (unsigned)j0;
    unsigned long long k1 =
        ((unsigned long long)__float_as_uint(v1) << 9) | (unsigned)j1;
    float x0 = x[base + j0], x1 = x[base + j1];
    float xr0 = low[j0] + (high[j0] - low[j0]) * r[base + j0];
    float xr1 = low[j1] + (high[j1] - low[j1]) * r[base + j1];
    float xc0 = (k0 < th) ? xr0 : x0;
    float xc1 = (k1 < th) ? xr1 : x1;

    __nv_bfloat16 h0, l0, h1, l1;
    split2(x0, h0, l0); split2(x1, h1, l1);
    *(uint32_t*)(xhi + base + j0) = pack2(h0, h1);
    *(uint32_t*)(xlo + base + j0) = pack2(l0, l1);
    split2(xc0, h0, l0); split2(xc1, h1, l1);
    *(uint32_t*)(xchi + base + j0) = pack2(h0, h1);
    *(uint32_t*)(xclo + base + j0) = pack2(l0, l1);
}

// ---------------------------------------------------------------------------
// Weight pack: W[K,256] -> bf16 B-fragment planes (hi, lo), v4-grouped:
// u32 index = (((c*2+ks)*16 + nfp)*32 + lane)*4 + reg4
//   c=k/32, ks=(k/16)&1, rem=k%16: b01=rem/8, tig=(rem%8)/2 (k-pair, even low)
//   nf=n/8, nfp=nf/2, reg4=(nf&1)*2+b01, lane=(n%8)*4+tig
// ---------------------------------------------------------------------------
__global__ void __launch_bounds__(256) pack_w_kernel(
    const float* __restrict__ W, uint32_t* __restrict__ WfHi,
    uint32_t* __restrict__ WfLo, int K)
{
    int idx = blockIdx.x * 256 + threadIdx.x;   // over (K/2)*256
    if (idx >= (K / 2) * HDIM) return;
    int k2 = idx >> 8;
    int n  = idx & 255;
    int k  = k2 * 2;
    __nv_bfloat16 h0, l0, h1, l1;
    split2(W[(size_t)k * HDIM + n], h0, l0);
    split2(W[(size_t)(k + 1) * HDIM + n], h1, l1);

    int c = k >> 5, ks = (k >> 4) & 1, rem = k & 15;
    int b01 = rem >> 3, tig = (rem & 7) >> 1;
    int nf = n >> 3, nfp = nf >> 1;
    int reg4 = ((nf & 1) << 1) | b01;
    int lane = ((n & 7) << 2) | tig;
    size_t i32 = ((((size_t)c * 2 + ks) * 16 + nfp) * 32 + lane) * 4 + reg4;
    WfHi[i32] = pack2(h0, h1);
    WfLo[i32] = pack2(l0, l1);
}

// ---------------------------------------------------------------------------
// bf16 split-3 GEMM, plane operands:
// C[128x128 tile of 256] = A @ W + bias.  8 warps (4m x 2n), BK=32,
// A via ldmatrix.x4 (80B-padded rows), B via lds.128 (2 n-frags/load),
// double-buffered cp.async.
// ---------------------------------------------------------------------------
#define OFF_AHI 0
#define OFF_ALO 10240
#define OFF_BHI 20480
#define OFF_BLO 28672
#define STAGE_B 36864
#define DSMEM_SZ (2 * STAGE_B + 512)

template <int K, bool RELU, bool PACKOUT>
__global__ void __launch_bounds__(256, 2) gemm_bf16x3(
    const __nv_bfloat16* __restrict__ AHi, const __nv_bfloat16* __restrict__ ALo,
    const __nv_bfloat16* __restrict__ A2Hi, const __nv_bfloat16* __restrict__ A2Lo,
    int rowsA,
    const uint32_t* __restrict__ WfHi, const uint32_t* __restrict__ WfLo,
    const float* __restrict__ bias,
    __nv_bfloat16* __restrict__ CHi, __nv_bfloat16* __restrict__ CLo,
    float* __restrict__ Cf)
{
    extern __shared__ __align__(16) char dsm[];
    const int tid  = threadIdx.x;
    const int lane = tid & 31;
    const int wid  = tid >> 5;
    const int wm   = wid >> 1;     // 0..3, 32 rows each
    const int wn   = wid & 1;      // 0..1, 64 cols each

    const int row0 = blockIdx.y * 128;
    const int col0 = blockIdx.x * 128;
    const int nfp0 = blockIdx.x * 8;

    const uint32_t base = smem_u32(dsm);
    float* s_bias = (float*)(dsm + 2 * STAGE_B);

    const __nv_bfloat16* Ah = AHi;
    const __nv_bfloat16* Al = ALo;
    int rb = row0;
    if (A2Hi != nullptr && row0 >= rowsA) { Ah = A2Hi; Al = A2Lo; rb = row0 - rowsA; }
    const __nv_bfloat16* AhG = Ah + (size_t)rb * K;
    const __nv_bfloat16* AlG = Al + (size_t)rb * K;

    if (tid < 128) s_bias[tid] = bias[col0 + tid];

    const int NC = K / 32;

    auto issue = [&](int c, int buf) {
        const uint32_t sb = base + buf * STAGE_B;
        // A planes: 512 units each (m = unit/4, uu = unit%4)
        #pragma unroll
        for (int i = 0; i < 2; i++) {
            int w = tid + i * 256;
            int m = w >> 2, uu = w & 3;
            CP_ASYNC16(sb + OFF_AHI + m * 80 + uu * 16,
                       AhG + (size_t)m * K + c * 32 + uu * 8);
        }
        #pragma unroll
        for (int i = 0; i < 2; i++) {
            int w = tid + i * 256;
            int m = w >> 2, uu = w & 3;
            CP_ASYNC16(sb + OFF_ALO + m * 80 + uu * 16,
                       AlG + (size_t)m * K + c * 32 + uu * 8);
        }
        // B planes: per plane 512 units [ks(2)][nfp(8)][lane(32)]
        #pragma unroll
        for (int i = 0; i < 2; i++) {   // ks = i
            size_t gi = ((((size_t)c * 2 + i) * 16 + nfp0 + (tid >> 5)) * 32
                         + (tid & 31)) * 4;
            CP_ASYNC16(sb + OFF_BHI + (i * 256 + tid) * 16, WfHi + gi);
        }
        #pragma unroll
        for (int i = 0; i < 2; i++) {
            size_t gi = ((((size_t)c * 2 + i) * 16 + nfp0 + (tid >> 5)) * 32
                         + (tid & 31)) * 4;
            CP_ASYNC16(sb + OFF_BLO + (i * 256 + tid) * 16, WfLo + gi);
        }
    };

    issue(0, 0);
    CP_COMMIT();
    CP_WAIT0();
    __syncthreads();

    float acc[2][8][4];
    #pragma unroll
    for (int mi = 0; mi < 2; mi++)
        #pragma unroll
        for (int ni = 0; ni < 8; ni++)
            #pragma unroll
            for (int j = 0; j < 4; j++) acc[mi][ni][j] = 0.0f;

    // ldmatrix lane-address component
    const uint32_t laddr = (uint32_t)((lane & 15) * 80 + (lane >> 4) * 16);

    for (int c = 0; c < NC; c++) {
        const int cur = c & 1;
        if (c + 1 < NC) { issue(c + 1, cur ^ 1); CP_COMMIT(); }
        const uint32_t sb = base + cur * STAGE_B;

        #pragma unroll
        for (int ks = 0; ks < 2; ks++) {
            uint32_t aHi[2][4], aLo[2][4];
            #pragma unroll
            for (int mi = 0; mi < 2; mi++) {
                const uint32_t tileOff =
                    (uint32_t)((wm * 32 + mi * 16) * 80 + ks * 32) + laddr;
                ldsm4(aHi[mi], sb + OFF_AHI + tileOff);
                ldsm4(aLo[mi], sb + OFF_ALO + tileOff);
            }
            #pragma unroll
            for (int p = 0; p < 4; p++) {
                const uint32_t boff =
                    (uint32_t)(((ks * 8 + wn * 4 + p) * 32 + lane) * 16);
                uint32_t bh[4], blo[4];
                asm volatile("ld.shared.v4.b32 {%0,%1,%2,%3}, [%4];"
                             : "=r"(bh[0]), "=r"(bh[1]), "=r"(bh[2]), "=r"(bh[3])
                             : "r"(sb + OFF_BHI + boff));
                asm volatile("ld.shared.v4.b32 {%0,%1,%2,%3}, [%4];"
                             : "=r"(blo[0]), "=r"(blo[1]), "=r"(blo[2]), "=r"(blo[3])
                             : "r"(sb + OFF_BLO + boff));
                #pragma unroll
                for (int h = 0; h < 2; h++) {   // 2 n-frags per v4
                    const int ni = p * 2 + h;
                    #pragma unroll
                    for (int mi = 0; mi < 2; mi++) {
                        mma_bf16(acc[mi][ni], aHi[mi], bh[h * 2], bh[h * 2 + 1]);
                        mma_bf16(acc[mi][ni], aHi[mi], blo[h * 2], blo[h * 2 + 1]);
                        mma_bf16(acc[mi][ni], aLo[mi], bh[h * 2], bh[h * 2 + 1]);
                    }
                }
            }
        }
        if (c + 1 < NC) { CP_WAIT0(); __syncthreads(); }
    }

    // ---- epilogue ----
    const int g8 = lane >> 2;
    const int tg = lane & 3;
    #pragma unroll
    for (int mi = 0; mi < 2; mi++) {
        const int m = row0 + wm * 32 + mi * 16 + g8;
        #pragma unroll
        for (int ni = 0; ni < 8; ni++) {
            const int nl = wn * 64 + ni * 8 + tg * 2;
            const float b0 = s_bias[nl], b1 = s_bias[nl + 1];
            float v0 = acc[mi][ni][0] + b0;
            float v1 = acc[mi][ni][1] + b1;
            float v2 = acc[mi][ni][2] + b0;
            float v3 = acc[mi][ni][3] + b1;
            if (RELU) {
                v0 = fmaxf(v0, 0.f); v1 = fmaxf(v1, 0.f);
                v2 = fmaxf(v2, 0.f); v3 = fmaxf(v3, 0.f);
            }
            const size_t i0 = (size_t)m * HDIM + col0 + nl;
            const size_t i1 = (size_t)(m + 8) * HDIM + col0 + nl;
            if (PACKOUT) {
                __nv_bfloat16 h0, l0, h1, l1;
                split2(v0, h0, l0); split2(v1, h1, l1);
                *(uint32_t*)(CHi + i0) = pack2(h0, h1);
                *(uint32_t*)(CLo + i0) = pack2(l0, l1);
                split2(v2, h0, l0); split2(v3, h1, l1);
                *(uint32_t*)(CHi + i1) = pack2(h0, h1);
                *(uint32_t*)(CLo + i1) = pack2(l0, l1);
            } else {
                *(float2*)(Cf + i0) = make_float2(v0, v1);
                *(float2*)(Cf + i1) = make_float2(v2, v3);
            }
        }
    }
}

// ---------------------------------------------------------------------------
// Launch
// ---------------------------------------------------------------------------
extern "C" void kernel_launch(void* const* d_in, const int* in_sizes, int n_in,
                              void* d_out, int out_size)
{
    const float *x = 0, *u = 0, *r = 0, *low = 0, *high = 0, *We0 = 0;
    const int* qptr = 0;
    const float* W65[8];  int nW = 0;
    const float* b256[8]; int nB = 0;

    for (int i = 0; i < n_in; i++) {
        int s = in_sizes[i];
        const float* p = (const float*)d_in[i];
        if (s == BROWS * MDIM) {
            if (!x) x = p; else if (!u) u = p; else if (!r) r = p;
        } else if (s == MDIM) {
            if (!low) low = p; else if (!high) high = p;
        } else if (s == 1) {
            qptr = (const int*)d_in[i];
        } else if (s == MDIM * HDIM) {
            We0 = p;
        } else if (s == HDIM * HDIM) {
            if (nW < 8) W65[nW++] = p;
        } else if (s == HDIM) {
            if (nB < 8) b256[nB++] = p;
        }
    }
    const float* bl[6] = {b256[0], b256[1], b256[2], b256[3], b256[4], b256[5]};

    __nv_bfloat16 *xhi = 0, *xlo = 0, *xchi = 0, *xclo = 0;
    __nv_bfloat16 *a0h = 0, *a0l = 0, *a1h = 0, *a1l = 0;
    uint32_t *w0p = 0, *wHp = 0;
    cudaGetSymbolAddress((void**)&xhi,  g_xhi);
    cudaGetSymbolAddress((void**)&xlo,  g_xlo);
    cudaGetSymbolAddress((void**)&xchi, g_xchi);
    cudaGetSymbolAddress((void**)&xclo, g_xclo);
    cudaGetSymbolAddress((void**)&a0h,  g_a0hi);
    cudaGetSymbolAddress((void**)&a0l,  g_a0lo);
    cudaGetSymbolAddress((void**)&a1h,  g_a1hi);
    cudaGetSymbolAddress((void**)&a1l,  g_a1lo);
    cudaGetSymbolAddress((void**)&w0p,  g_Wf0p);
    cudaGetSymbolAddress((void**)&wHp,  g_WfHp);
    float* out = (float*)d_out;

    const size_t W0PL = (size_t)MDIM * 128;
    const size_t WHPL = (size_t)HDIM * 128;
    uint32_t* w0hi = w0p;
    uint32_t* w0lo = w0p + W0PL;
    auto whi = [&](int i) { return wHp + (size_t)i * 2 * WHPL; };
    auto wlo = [&](int i) { return wHp + (size_t)i * 2 * WHPL + WHPL; };

    cudaFuncSetAttribute(gemm_bf16x3<MDIM, true,  true >, cudaFuncAttributeMaxDynamicSharedMemorySize, DSMEM_SZ);
    cudaFuncSetAttribute(gemm_bf16x3<HDIM, true,  true >, cudaFuncAttributeMaxDynamicSharedMemorySize, DSMEM_SZ);
    cudaFuncSetAttribute(gemm_bf16x3<HDIM, false, true >, cudaFuncAttributeMaxDynamicSharedMemorySize, DSMEM_SZ);
    cudaFuncSetAttribute(gemm_bf16x3<HDIM, false, false>, cudaFuncAttributeMaxDynamicSharedMemorySize, DSMEM_SZ);

    // 1) corruption + split-plane emit
    corrupt_kernel<<<BROWS, 256>>>(x, u, r, low, high, qptr, 307,
                                   xhi, xlo, xchi, xclo);

    // 2) weight fragment-packing (tiny)
    pack_w_kernel<<<(MDIM / 2 * HDIM) / 256, 256>>>(We0, w0hi, w0lo, MDIM);
    for (int i = 0; i < 5; i++)
        pack_w_kernel<<<(HDIM / 2 * HDIM) / 256, 256>>>(W65[i], whi(i), wlo(i), HDIM);

    // 3) 6 layers, bf16 split-3 tensor cores, both branches stacked
    dim3 grid(HDIM / 128, TOTROWS / 128);   // (2, 512)
    dim3 blk(256);
    const __nv_bfloat16* NB = (const __nv_bfloat16*)0;

    gemm_bf16x3<MDIM, true,  true ><<<grid, blk, DSMEM_SZ>>>(
        xhi, xlo, xchi, xclo, BROWS, w0hi, w0lo, bl[0], a0h, a0l, (float*)0);
    gemm_bf16x3<HDIM, true,  true ><<<grid, blk, DSMEM_SZ>>>(
        a0h, a0l, NB, NB, TOTROWS, whi(0), wlo(0), bl[1], a1h, a1l, (float*)0);
    gemm_bf16x3<HDIM, true,  true ><<<grid, blk, DSMEM_SZ>>>(
        a1h, a1l, NB, NB, TOTROWS, whi(1), wlo(1), bl[2], a0h, a0l, (float*)0);
    gemm_bf16x3<HDIM, false, true ><<<grid, blk, DSMEM_SZ>>>(
        a0h, a0l, NB, NB, TOTROWS, whi(2), wlo(2), bl[3], a1h, a1l, (float*)0);
    gemm_bf16x3<HDIM, true,  true ><<<grid, blk, DSMEM_SZ>>>(
        a1h, a1l, NB, NB, TOTROWS, whi(3), wlo(3), bl[4], a0h, a0l, (float*)0);
    gemm_bf16x3<HDIM, false, false><<<grid, blk, DSMEM_SZ>>>(
        a0h, a0l, NB, NB, TOTROWS, whi(4), wlo(4), bl[5],
        (__nv_bfloat16*)0, (__nv_bfloat16*)0, out);

    (void)out_size;
}